// round 3
// baseline (speedup 1.0000x reference)
#include <cuda_runtime.h>
#include <cstdint>

#define NN 50000
#define NE 800000
#define HID 64

// ---------------- scratch (device globals; no allocations allowed) ----------
__device__ __align__(16) float g_q[NN * HID];
__device__ __align__(16) float g_k[NN * HID];
__device__ __align__(16) float g_v[NN * HID];
__device__ __align__(16) float g_skip[NN * HID];
__device__ __align__(16) float g_agg[NN * HID];
__device__ __align__(16) float g_m[NN];
__device__ __align__(16) float g_s[NN];
__device__ __align__(16) float g_logit[NE];
__device__ __align__(16) float g_eL[NE * 5];

#define NEG_INF __int_as_float(0xff800000)

__device__ __forceinline__ void atomicMaxF(float* addr, float val) {
    // Monotone-bits trick; init must be -inf (0xff800000).
    if (val >= 0.0f) atomicMax((int*)addr, __float_as_int(val));
    else             atomicMin((unsigned int*)addr, __float_as_uint(val));
}

// ---------------- prep: log1p(edge_attr) ------------------------------------
__global__ void kprep(const float* __restrict__ ea) {
    int i = blockIdx.x * blockDim.x + threadIdx.x;
    int stride = gridDim.x * blockDim.x;
    for (int t = i; t < NE * 5; t += stride) {
        g_eL[t] = log1pf(ea[t]);
    }
}

// ---------------- K1: per-layer node GEMM (q,k,v,skip fused) ---------------
// mode 0: h = log1p(x[n, 0..kin))            (layer 0, kin=10)
// mode 1: h = g_agg/g_s + g_skip  (fused epilogue of previous layer, kin=64)
// Also resets g_agg, g_s, g_m for the upcoming edge passes.
__global__ __launch_bounds__(256) void k1_node(
    const float* __restrict__ xin, int kin, int mode,
    const float* __restrict__ wq, const float* __restrict__ bq,
    const float* __restrict__ wk, const float* __restrict__ bk,
    const float* __restrict__ wv, const float* __restrict__ bv,
    const float* __restrict__ wsk, const float* __restrict__ bsk)
{
    extern __shared__ float smbuf[];
    const int HS = kin + 1;                 // padded h row stride
    float* hs = smbuf;                      // 64 * HS
    float* Ws = smbuf + 64 * HS;            // kin * 256
    float* Bs = Ws + kin * 256;             // 256
    __shared__ float sinv[64];

    const int t = threadIdx.x;
    const int base = blockIdx.x * 64;

    // ---- load weights (4 matrices concatenated: col cc = mtx*64 + j) ----
    {
        const float* wptr[4] = {wq, wk, wv, wsk};
        for (int idx = t; idx < kin * 256; idx += 256) {
            int kk = idx >> 8, cc = idx & 255;
            Ws[idx] = wptr[cc >> 6][kk * 64 + (cc & 63)];
        }
        const float* bptr[4] = {bq, bk, bv, bsk};
        Bs[t] = bptr[t >> 6][t & 63];
    }

    // ---- per-node state: read s, reset s/m ----
    if (t < 64) {
        int n = base + t;
        if (n < NN) {
            float sv = (mode == 1) ? g_s[n] : 0.0f;
            sinv[t] = (sv > 0.0f) ? 1.0f / sv : 0.0f;
            g_s[n] = 0.0f;
            g_m[n] = NEG_INF;
        } else {
            sinv[t] = 0.0f;
        }
    }
    __syncthreads();

    // ---- load h tile; zero agg for this layer ----
    if (mode == 0) {
        for (int idx = t; idx < 64 * kin; idx += 256) {
            int r = idx / kin, c = idx - r * kin;
            int n = base + r;
            hs[r * HS + c] = (n < NN) ? log1pf(xin[n * 10 + c]) : 0.0f;
        }
        for (int idx = t; idx < 64 * 64; idx += 256) {
            int r = idx >> 6, c = idx & 63;
            int n = base + r;
            if (n < NN) g_agg[(size_t)n * 64 + c] = 0.0f;
        }
    } else {
        for (int idx = t; idx < 64 * 64; idx += 256) {
            int r = idx >> 6, c = idx & 63;
            int n = base + r;
            float val = 0.0f;
            if (n < NN) {
                size_t o = (size_t)n * 64 + c;
                val = g_agg[o] * sinv[r] + g_skip[o];
                g_agg[o] = 0.0f;
            }
            hs[r * HS + c] = val;
        }
    }
    __syncthreads();

    // ---- compute: 8 nodes x 8 cols per thread ----
    const int tc = t & 31;       // cols handled: tc + 32*j
    const int tr = t >> 5;       // nodes handled: tr*8 + i
    float acc[8][8];
    #pragma unroll
    for (int j = 0; j < 8; j++) {
        float b = Bs[tc + 32 * j];
        #pragma unroll
        for (int i = 0; i < 8; i++) acc[i][j] = b;
    }
    for (int kk = 0; kk < kin; kk++) {
        float hv[8], wv2[8];
        #pragma unroll
        for (int i = 0; i < 8; i++) hv[i] = hs[(tr * 8 + i) * HS + kk];
        #pragma unroll
        for (int j = 0; j < 8; j++) wv2[j] = Ws[kk * 256 + tc + 32 * j];
        #pragma unroll
        for (int i = 0; i < 8; i++)
            #pragma unroll
            for (int j = 0; j < 8; j++) acc[i][j] += hv[i] * wv2[j];
    }

    // ---- writeback ----
    #pragma unroll
    for (int i = 0; i < 8; i++) {
        int n = base + tr * 8 + i;
        if (n >= NN) continue;
        #pragma unroll
        for (int j = 0; j < 8; j++) {
            int cc = tc + 32 * j;
            float* op = (cc < 64) ? g_q : (cc < 128) ? g_k : (cc < 192) ? g_v : g_skip;
            op[(size_t)n * 64 + (cc & 63)] = acc[i][j];
        }
    }
}

// ---------------- K2: edge logits + segment max ----------------------------
// Half-warp (16 lanes) per edge; lane l16 covers cols [4*l16, 4*l16+4).
__global__ __launch_bounds__(256) void k2_logit(const int* __restrict__ ei,
                                                const float* __restrict__ we)
{
    int tid = blockIdx.x * blockDim.x + threadIdx.x;
    int e = tid >> 4;
    int lane = threadIdx.x & 31;
    int l16 = lane & 15;
    unsigned mask = 0xFFFFu << (lane & 16);
    if (e >= NE) return;

    float wr[5][4];
    #pragma unroll
    for (int d = 0; d < 5; d++) {
        float4 w4 = *(const float4*)(we + d * 64 + l16 * 4);
        wr[d][0] = w4.x; wr[d][1] = w4.y; wr[d][2] = w4.z; wr[d][3] = w4.w;
    }

    int sn = ei[e], dn = ei[NE + e];
    float4 qv = *(const float4*)(g_q + (size_t)dn * 64 + l16 * 4);
    float4 kv = *(const float4*)(g_k + (size_t)sn * 64 + l16 * 4);
    float e0 = g_eL[e * 5 + 0], e1 = g_eL[e * 5 + 1], e2 = g_eL[e * 5 + 2],
          e3 = g_eL[e * 5 + 3], e4 = g_eL[e * 5 + 4];

    float ee0 = e0 * wr[0][0] + e1 * wr[1][0] + e2 * wr[2][0] + e3 * wr[3][0] + e4 * wr[4][0];
    float ee1 = e0 * wr[0][1] + e1 * wr[1][1] + e2 * wr[2][1] + e3 * wr[3][1] + e4 * wr[4][1];
    float ee2 = e0 * wr[0][2] + e1 * wr[1][2] + e2 * wr[2][2] + e3 * wr[3][2] + e4 * wr[4][2];
    float ee3 = e0 * wr[0][3] + e1 * wr[1][3] + e2 * wr[2][3] + e3 * wr[3][3] + e4 * wr[4][3];

    float part = qv.x * (kv.x + ee0) + qv.y * (kv.y + ee1)
               + qv.z * (kv.z + ee2) + qv.w * (kv.w + ee3);
    part += __shfl_xor_sync(mask, part, 8);
    part += __shfl_xor_sync(mask, part, 4);
    part += __shfl_xor_sync(mask, part, 2);
    part += __shfl_xor_sync(mask, part, 1);

    if (l16 == 0) {
        float lg = part * 0.125f;         // / sqrt(64)
        g_logit[e] = lg;
        atomicMaxF(&g_m[dn], lg);
    }
}

// ---------------- K3: p = exp(logit - m), accumulate s and p*(v+ee) --------
__global__ __launch_bounds__(256) void k3_agg(const int* __restrict__ ei,
                                              const float* __restrict__ we)
{
    int tid = blockIdx.x * blockDim.x + threadIdx.x;
    int e = tid >> 4;
    int lane = threadIdx.x & 31;
    int l16 = lane & 15;
    if (e >= NE) return;

    float wr[5][4];
    #pragma unroll
    for (int d = 0; d < 5; d++) {
        float4 w4 = *(const float4*)(we + d * 64 + l16 * 4);
        wr[d][0] = w4.x; wr[d][1] = w4.y; wr[d][2] = w4.z; wr[d][3] = w4.w;
    }

    int sn = ei[e], dn = ei[NE + e];
    float p = __expf(g_logit[e] - g_m[dn]);
    if (l16 == 0) atomicAdd(&g_s[dn], p);

    float4 vv = *(const float4*)(g_v + (size_t)sn * 64 + l16 * 4);
    float e0 = g_eL[e * 5 + 0], e1 = g_eL[e * 5 + 1], e2 = g_eL[e * 5 + 2],
          e3 = g_eL[e * 5 + 3], e4 = g_eL[e * 5 + 4];

    float4 r;
    r.x = p * (vv.x + e0 * wr[0][0] + e1 * wr[1][0] + e2 * wr[2][0] + e3 * wr[3][0] + e4 * wr[4][0]);
    r.y = p * (vv.y + e0 * wr[0][1] + e1 * wr[1][1] + e2 * wr[2][1] + e3 * wr[3][1] + e4 * wr[4][1]);
    r.z = p * (vv.z + e0 * wr[0][2] + e1 * wr[1][2] + e2 * wr[2][2] + e3 * wr[3][2] + e4 * wr[4][2]);
    r.w = p * (vv.w + e0 * wr[0][3] + e1 * wr[1][3] + e2 * wr[2][3] + e3 * wr[3][3] + e4 * wr[4][3]);

    float* ap = g_agg + (size_t)dn * 64 + l16 * 4;
    asm volatile("red.global.add.v4.f32 [%0], {%1,%2,%3,%4};"
                 :: "l"(ap), "f"(r.x), "f"(r.y), "f"(r.z), "f"(r.w) : "memory");
}

// ---------------- final: out = (agg/s + skip) @ lin_w + lin_b --------------
__global__ __launch_bounds__(256) void kfinal(const float* __restrict__ lw,
                                              const float* __restrict__ lb,
                                              float* __restrict__ out)
{
    int w = (blockIdx.x * blockDim.x + threadIdx.x) >> 5;
    int lane = threadIdx.x & 31;
    if (w >= NN) return;
    float sv = g_s[w];
    float inv = (sv > 0.0f) ? 1.0f / sv : 0.0f;
    float2 a  = *(const float2*)(g_agg  + (size_t)w * 64 + lane * 2);
    float2 sk = *(const float2*)(g_skip + (size_t)w * 64 + lane * 2);
    float2 wv = *(const float2*)(lw + lane * 2);
    float part = (a.x * inv + sk.x) * wv.x + (a.y * inv + sk.y) * wv.y;
    #pragma unroll
    for (int o = 16; o; o >>= 1) part += __shfl_xor_sync(0xffffffffu, part, o);
    if (lane == 0) out[w] = part + lb[0];
}

// ---------------- driver ----------------------------------------------------
extern "C" void kernel_launch(void* const* d_in, const int* in_sizes, int n_in,
                              void* d_out, int out_size)
{
    const float* x   = (const float*)d_in[0];
    const int*   ei  = (const int*)d_in[1];       // int32: jax x64 is disabled
    const float* ea  = (const float*)d_in[2];
    const float* w1q = (const float*)d_in[3];  const float* b1q = (const float*)d_in[4];
    const float* w1k = (const float*)d_in[5];  const float* b1k = (const float*)d_in[6];
    const float* w1v = (const float*)d_in[7];  const float* b1v = (const float*)d_in[8];
    const float* w1e = (const float*)d_in[9];
    const float* w1s = (const float*)d_in[10]; const float* b1s = (const float*)d_in[11];
    const float* wq  = (const float*)d_in[12]; const float* bq  = (const float*)d_in[13];
    const float* wk  = (const float*)d_in[14]; const float* bk  = (const float*)d_in[15];
    const float* wv  = (const float*)d_in[16]; const float* bv  = (const float*)d_in[17];
    const float* we  = (const float*)d_in[18];
    const float* ws  = (const float*)d_in[19]; const float* bs  = (const float*)d_in[20];
    const float* lw  = (const float*)d_in[21]; const float* lb  = (const float*)d_in[22];
    float* out = (float*)d_out;

    // >48KB dynamic smem for the 64-in GEMM (83.2 KB)
    cudaFuncSetAttribute(k1_node, cudaFuncAttributeMaxDynamicSharedMemorySize, 100 * 1024);

    const int nb1 = (NN + 63) / 64;
    const size_t smem10 = (size_t)(64 * 11 + 10 * 256 + 256) * sizeof(float);
    const size_t smem64 = (size_t)(64 * 65 + 64 * 256 + 256) * sizeof(float);
    const int nbE = NE / 16;   // 16 edges per 256-thread block (half-warp/edge)
    const int nbF = (NN * 32 + 255) / 256;

    kprep<<<512, 256>>>(ea);

    // layer 0 (10 -> 64)
    k1_node<<<nb1, 256, smem10>>>(x, 10, 0, w1q, b1q, w1k, b1k, w1v, b1v, w1s, b1s);
    k2_logit<<<nbE, 256>>>(ei, w1e);
    k3_agg<<<nbE, 256>>>(ei, w1e);

    // layers 1..5 (64 -> 64)
    for (int l = 0; l < 5; l++) {
        k1_node<<<nb1, 256, smem64>>>(nullptr, 64, 1,
                                      wq + l * 4096, bq + l * 64,
                                      wk + l * 4096, bk + l * 64,
                                      wv + l * 4096, bv + l * 64,
                                      ws + l * 4096, bs + l * 64);
        k2_logit<<<nbE, 256>>>(ei, we + l * 320);
        k3_agg<<<nbE, 256>>>(ei, we + l * 320);
    }

    kfinal<<<nbF, 256>>>(lw, lb, out);
}

// round 4
// speedup vs baseline: 1.4138x; 1.4138x over previous
#include <cuda_runtime.h>
#include <cstdint>

#define NN 50000
#define NE 800000
#define HID 64

// ---------------- scratch (device globals; no allocations allowed) ----------
__device__ __align__(16) float g_q[NN * HID];
__device__ __align__(16) float g_k[NN * HID];
__device__ __align__(16) float g_v[NN * HID];
__device__ __align__(16) float g_skip[NN * HID];
__device__ __align__(16) float g_agg[NN * HID];     // h between layers
__device__ __align__(16) float g_logit[NE];
__device__ __align__(16) float g_eLs[NE * 5];       // log1p(edge_attr), sorted by dst
__device__ __align__(16) int   g_srcs[NE];          // src node, sorted by dst
__device__ __align__(16) int   g_rowptr[NN + 1];
__device__ __align__(16) int   g_cnt[NN];

#define NEG_INF __int_as_float(0xff800000)

// ---------------- CSR build: zero, histogram, scan, scatter ----------------
__global__ void kzero() {
    int i = blockIdx.x * blockDim.x + threadIdx.x;
    if (i < NN) g_cnt[i] = 0;
}

__global__ void khist(const int* __restrict__ ei) {
    int e = blockIdx.x * blockDim.x + threadIdx.x;
    if (e < NE) atomicAdd(&g_cnt[ei[NE + e]], 1);
}

// single-block exclusive scan over g_cnt -> g_rowptr; re-zeros g_cnt
__global__ __launch_bounds__(1024) void kscan() {
    const int t = threadIdx.x;
    const int lane = t & 31, wid = t >> 5;
    __shared__ int warp_sums[32];
    __shared__ int carry_s;
    if (t == 0) carry_s = 0;
    __syncthreads();
    for (int base = 0; base < NN; base += 1024) {
        int i = base + t;
        int v = (i < NN) ? g_cnt[i] : 0;
        if (i < NN) g_cnt[i] = 0;        // reset for scatter ranks
        int x = v;
        #pragma unroll
        for (int o = 1; o < 32; o <<= 1) {
            int y = __shfl_up_sync(0xffffffffu, x, o);
            if (lane >= o) x += y;
        }
        if (lane == 31) warp_sums[wid] = x;
        __syncthreads();
        if (wid == 0) {
            int ws = warp_sums[lane];
            #pragma unroll
            for (int o = 1; o < 32; o <<= 1) {
                int y = __shfl_up_sync(0xffffffffu, ws, o);
                if (lane >= o) ws += y;
            }
            warp_sums[lane] = ws;
        }
        __syncthreads();
        int incl = x + (wid > 0 ? warp_sums[wid - 1] : 0);
        if (i < NN) g_rowptr[i] = incl - v + carry_s;
        __syncthreads();
        if (t == 1023) carry_s += incl;
        __syncthreads();
    }
    if (t == 0) g_rowptr[NN] = carry_s;
}

__global__ void kscatter(const int* __restrict__ ei, const float* __restrict__ ea) {
    int e = blockIdx.x * blockDim.x + threadIdx.x;
    if (e >= NE) return;
    int sn = ei[e], dn = ei[NE + e];
    int pos = g_rowptr[dn] + atomicAdd(&g_cnt[dn], 1);
    g_srcs[pos] = sn;
    #pragma unroll
    for (int d = 0; d < 5; d++)
        g_eLs[pos * 5 + d] = log1pf(ea[e * 5 + d]);
}

// ---------------- K1: per-layer node GEMM (q,k,v,skip fused) ---------------
// mode 0: h = log1p(x[n,0..kin))   (layer 0, kin=10)
// mode 1: h = g_agg (written fully normalized by kedge of previous layer)
__global__ __launch_bounds__(256) void k1_node(
    const float* __restrict__ xin, int kin, int mode,
    const float* __restrict__ wq, const float* __restrict__ bq,
    const float* __restrict__ wk, const float* __restrict__ bk,
    const float* __restrict__ wv, const float* __restrict__ bv,
    const float* __restrict__ wsk, const float* __restrict__ bsk)
{
    extern __shared__ float smbuf[];
    const int HS = kin + 1;
    float* hs = smbuf;                      // 64 * HS
    float* Ws = smbuf + 64 * HS;            // kin * 256
    float* Bs = Ws + kin * 256;             // 256

    const int t = threadIdx.x;
    const int base = blockIdx.x * 64;

    {
        const float* wptr[4] = {wq, wk, wv, wsk};
        for (int idx = t; idx < kin * 256; idx += 256) {
            int kk = idx >> 8, cc = idx & 255;
            Ws[idx] = wptr[cc >> 6][kk * 64 + (cc & 63)];
        }
        const float* bptr[4] = {bq, bk, bv, bsk};
        Bs[t] = bptr[t >> 6][t & 63];
    }

    if (mode == 0) {
        for (int idx = t; idx < 64 * kin; idx += 256) {
            int r = idx / kin, c = idx - r * kin;
            int n = base + r;
            hs[r * HS + c] = (n < NN) ? log1pf(xin[n * 10 + c]) : 0.0f;
        }
    } else {
        for (int idx = t; idx < 64 * 64; idx += 256) {
            int r = idx >> 6, c = idx & 63;
            int n = base + r;
            hs[r * HS + c] = (n < NN) ? g_agg[(size_t)n * 64 + c] : 0.0f;
        }
    }
    __syncthreads();

    const int tc = t & 31;
    const int tr = t >> 5;
    float acc[8][8];
    #pragma unroll
    for (int j = 0; j < 8; j++) {
        float b = Bs[tc + 32 * j];
        #pragma unroll
        for (int i = 0; i < 8; i++) acc[i][j] = b;
    }
    for (int kk = 0; kk < kin; kk++) {
        float hv[8], wv2[8];
        #pragma unroll
        for (int i = 0; i < 8; i++) hv[i] = hs[(tr * 8 + i) * HS + kk];
        #pragma unroll
        for (int j = 0; j < 8; j++) wv2[j] = Ws[kk * 256 + tc + 32 * j];
        #pragma unroll
        for (int i = 0; i < 8; i++)
            #pragma unroll
            for (int j = 0; j < 8; j++) acc[i][j] += hv[i] * wv2[j];
    }

    #pragma unroll
    for (int i = 0; i < 8; i++) {
        int n = base + tr * 8 + i;
        if (n >= NN) continue;
        #pragma unroll
        for (int j = 0; j < 8; j++) {
            int cc = tc + 32 * j;
            float* op = (cc < 64) ? g_q : (cc < 128) ? g_k : (cc < 192) ? g_v : g_skip;
            op[(size_t)n * 64 + (cc & 63)] = acc[i][j];
        }
    }
}

// ---------------- kedge: warp-per-node fused attention ---------------------
// loop1: logits + running max; loop2: p=exp, s, weighted agg.
// Writes h_next = agg/s + skip directly into g_agg. No atomics anywhere.
__global__ __launch_bounds__(256) void kedge(const float* __restrict__ we)
{
    int n = (blockIdx.x * 256 + threadIdx.x) >> 5;
    int lane = threadIdx.x & 31;
    if (n >= NN) return;

    float wr[5][2];
    #pragma unroll
    for (int d = 0; d < 5; d++) {
        float2 w2 = *(const float2*)(we + d * 64 + lane * 2);
        wr[d][0] = w2.x; wr[d][1] = w2.y;
    }

    const int start = g_rowptr[n];
    const int end   = g_rowptr[n + 1];
    float2 sk = *(const float2*)(g_skip + (size_t)n * 64 + lane * 2);

    if (start == end) {   // degree 0: h = skip
        *(float2*)(g_agg + (size_t)n * 64 + lane * 2) = sk;
        return;
    }

    float2 qv = *(const float2*)(g_q + (size_t)n * 64 + lane * 2);

    float m = NEG_INF;
    for (int p0 = start; p0 < end; p0++) {
        int sn = __ldg(g_srcs + p0);
        float2 kv = *(const float2*)(g_k + (size_t)sn * 64 + lane * 2);
        float e0 = __ldg(g_eLs + p0 * 5 + 0), e1 = __ldg(g_eLs + p0 * 5 + 1),
              e2 = __ldg(g_eLs + p0 * 5 + 2), e3 = __ldg(g_eLs + p0 * 5 + 3),
              e4 = __ldg(g_eLs + p0 * 5 + 4);
        float ee0 = e0*wr[0][0] + e1*wr[1][0] + e2*wr[2][0] + e3*wr[3][0] + e4*wr[4][0];
        float ee1 = e0*wr[0][1] + e1*wr[1][1] + e2*wr[2][1] + e3*wr[3][1] + e4*wr[4][1];
        float part = qv.x * (kv.x + ee0) + qv.y * (kv.y + ee1);
        part += __shfl_xor_sync(0xffffffffu, part, 16);
        part += __shfl_xor_sync(0xffffffffu, part, 8);
        part += __shfl_xor_sync(0xffffffffu, part, 4);
        part += __shfl_xor_sync(0xffffffffu, part, 2);
        part += __shfl_xor_sync(0xffffffffu, part, 1);
        float lg = part * 0.125f;
        if (lane == 0) g_logit[p0] = lg;
        m = fmaxf(m, lg);
    }
    __syncwarp();   // make lane0's logit stores visible to all lanes

    float s = 0.0f, a0 = 0.0f, a1 = 0.0f;
    for (int p0 = start; p0 < end; p0++) {
        int sn = __ldg(g_srcs + p0);
        float2 vv = *(const float2*)(g_v + (size_t)sn * 64 + lane * 2);
        float e0 = __ldg(g_eLs + p0 * 5 + 0), e1 = __ldg(g_eLs + p0 * 5 + 1),
              e2 = __ldg(g_eLs + p0 * 5 + 2), e3 = __ldg(g_eLs + p0 * 5 + 3),
              e4 = __ldg(g_eLs + p0 * 5 + 4);
        float ee0 = e0*wr[0][0] + e1*wr[1][0] + e2*wr[2][0] + e3*wr[3][0] + e4*wr[4][0];
        float ee1 = e0*wr[0][1] + e1*wr[1][1] + e2*wr[2][1] + e3*wr[3][1] + e4*wr[4][1];
        float p = __expf(__ldg(g_logit + p0) - m);
        s  += p;
        a0 += p * (vv.x + ee0);
        a1 += p * (vv.y + ee1);
    }
    float inv = 1.0f / s;   // s >= 1 (max term contributes exp(0)=1)
    float2 h;
    h.x = a0 * inv + sk.x;
    h.y = a1 * inv + sk.y;
    *(float2*)(g_agg + (size_t)n * 64 + lane * 2) = h;
}

// ---------------- final: out = h @ lin_w + lin_b ---------------------------
__global__ __launch_bounds__(256) void kfinal(const float* __restrict__ lw,
                                              const float* __restrict__ lb,
                                              float* __restrict__ out)
{
    int n = (blockIdx.x * blockDim.x + threadIdx.x) >> 5;
    int lane = threadIdx.x & 31;
    if (n >= NN) return;
    float2 h  = *(const float2*)(g_agg + (size_t)n * 64 + lane * 2);
    float2 wv = *(const float2*)(lw + lane * 2);
    float part = h.x * wv.x + h.y * wv.y;
    #pragma unroll
    for (int o = 16; o; o >>= 1) part += __shfl_xor_sync(0xffffffffu, part, o);
    if (lane == 0) out[n] = part + lb[0];
}

// ---------------- driver ----------------------------------------------------
extern "C" void kernel_launch(void* const* d_in, const int* in_sizes, int n_in,
                              void* d_out, int out_size)
{
    const float* x   = (const float*)d_in[0];
    const int*   ei  = (const int*)d_in[1];       // int32 (jax x64 disabled)
    const float* ea  = (const float*)d_in[2];
    const float* w1q = (const float*)d_in[3];  const float* b1q = (const float*)d_in[4];
    const float* w1k = (const float*)d_in[5];  const float* b1k = (const float*)d_in[6];
    const float* w1v = (const float*)d_in[7];  const float* b1v = (const float*)d_in[8];
    const float* w1e = (const float*)d_in[9];
    const float* w1s = (const float*)d_in[10]; const float* b1s = (const float*)d_in[11];
    const float* wq  = (const float*)d_in[12]; const float* bq  = (const float*)d_in[13];
    const float* wk  = (const float*)d_in[14]; const float* bk  = (const float*)d_in[15];
    const float* wv  = (const float*)d_in[16]; const float* bv  = (const float*)d_in[17];
    const float* we  = (const float*)d_in[18];
    const float* ws  = (const float*)d_in[19]; const float* bs  = (const float*)d_in[20];
    const float* lw  = (const float*)d_in[21]; const float* lb  = (const float*)d_in[22];
    float* out = (float*)d_out;

    cudaFuncSetAttribute(k1_node, cudaFuncAttributeMaxDynamicSharedMemorySize, 100 * 1024);

    const int nb1 = (NN + 63) / 64;
    const size_t smem10 = (size_t)(64 * 11 + 10 * 256 + 256) * sizeof(float);
    const size_t smem64 = (size_t)(64 * 65 + 64 * 256 + 256) * sizeof(float);
    const int nbN = (NN + 255) / 256;
    const int nbE = (NE + 255) / 256;
    const int nbW = (NN * 32 + 255) / 256;   // warp-per-node grids

    // build CSR (edge_index is constant; rebuilt identically each replay)
    kzero<<<nbN, 256>>>();
    khist<<<nbE, 256>>>(ei);
    kscan<<<1, 1024>>>();
    kscatter<<<nbE, 256>>>(ei, ea);

    // layer 0 (10 -> 64)
    k1_node<<<nb1, 256, smem10>>>(x, 10, 0, w1q, b1q, w1k, b1k, w1v, b1v, w1s, b1s);
    kedge<<<nbW, 256>>>(w1e);

    // layers 1..5 (64 -> 64)
    for (int l = 0; l < 5; l++) {
        k1_node<<<nb1, 256, smem64>>>(nullptr, 64, 1,
                                      wq + l * 4096, bq + l * 64,
                                      wk + l * 4096, bk + l * 64,
                                      wv + l * 4096, bv + l * 64,
                                      ws + l * 4096, bs + l * 64);
        kedge<<<nbW, 256>>>(we + l * 320);
    }

    kfinal<<<nbW, 256>>>(lw, lb, out);
}